// round 5
// baseline (speedup 1.0000x reference)
#include <cuda_runtime.h>
#include <math.h>

// Problem constants
#define LQ 2048
#define DM 1024
#define NG 4              // query groups
#define NH 4              // heads per group
#define HD 64             // head dim
#define GC 256            // per-group channel count (NH*HD)
#define SCALE 0.125f      // 64^-0.5
#define LN_EPS 1e-5f

// ---------------- scratch (device globals: allocation-free) ----------------
__device__ float g_Q[LQ * DM];                       // 8 MB   [l][g*256+c]
__device__ float g_KV[LQ * 2 * DM];                  // 16 MB  [l][head*128 + s*64 + d]
__device__ float g_Vt[GC * NG * LQ];                 // 8 MB   [c][G*2048+k]
__device__ float g_S[(size_t)NG * LQ * NG * LQ];     // 256 MB [g][m][G][k]
__device__ float g_O[LQ * DM];                       // 8 MB   [m][g*256+c]
__device__ float g_P[LQ * DM];                       // 8 MB

// ---------------- packed f32x2 helpers ----------------
__device__ __forceinline__ unsigned long long pack_rep(float a) {
    unsigned long long r;
    asm("mov.b64 %0, {%1, %1};" : "=l"(r) : "f"(a));
    return r;
}
__device__ __forceinline__ unsigned long long fma2(unsigned long long a,
                                                   unsigned long long b,
                                                   unsigned long long c) {
    unsigned long long d;
    asm("fma.rn.f32x2 %0, %1, %2, %3;" : "=l"(d) : "l"(a), "l"(b), "l"(c));
    return d;
}
__device__ __forceinline__ float2 unpack2(unsigned long long v) {
    float2 f;
    asm("mov.b64 {%0, %1}, %2;" : "=f"(f.x), "=f"(f.y) : "l"(v));
    return f;
}

// ---------------- 64x64 SGEMM tile:  C = alpha * A(MxK) * B(NxK)^T ----------------
// blockDim = 256. blockIdx.x -> N tile, blockIdx.y -> M tile.
// remap_b: if nonzero, B columns are addressed via the K-head interleave
//          col = bcol0 + (c>>6)*128 + (c&63)  (fuses the K-split re-layout).
// All dims are multiples of tile sizes for this problem (no bounds checks).
__device__ __forceinline__ void gemm_tile_64x64(
    const float* __restrict__ A, int lda,
    const float* __restrict__ B, int ldb,
    float* __restrict__ C, int ldc,
    int K, float alpha, int remap_b, int bcol0)
{
    __shared__ __align__(16) float As[16][68];
    __shared__ __align__(16) float Bs[16][68];

    const int t  = threadIdx.x;
    const int tx = t & 15;     // n sub-tile
    const int ty = t >> 4;     // m sub-tile
    const int m0 = blockIdx.y * 64;
    const int n0 = blockIdx.x * 64;

    unsigned long long acc[4][2];
#pragma unroll
    for (int i = 0; i < 4; i++) { acc[i][0] = 0ull; acc[i][1] = 0ull; }

    for (int k0 = 0; k0 < K; k0 += 16) {
#pragma unroll
        for (int j = 0; j < 4; j++) {
            int i  = t + j * 256;          // 0..1023 over 64x16 tile
            int mm = i >> 4;
            int kk = i & 15;
            As[kk][mm] = A[(size_t)(m0 + mm) * lda + k0 + kk];
            int c = k0 + kk;
            int bc = remap_b ? (bcol0 + ((c >> 6) * 128) + (c & 63)) : c;
            Bs[kk][mm] = B[(size_t)(n0 + mm) * ldb + bc];
        }
        __syncthreads();
#pragma unroll
        for (int kk = 0; kk < 16; kk++) {
            float4 a4 = *(const float4*)&As[kk][ty * 4];
            ulonglong2 b = *(const ulonglong2*)&Bs[kk][tx * 4];
            float av[4] = {a4.x, a4.y, a4.z, a4.w};
#pragma unroll
            for (int ii = 0; ii < 4; ii++) {
                unsigned long long aa = pack_rep(av[ii]);
                acc[ii][0] = fma2(aa, b.x, acc[ii][0]);
                acc[ii][1] = fma2(aa, b.y, acc[ii][1]);
            }
        }
        __syncthreads();
    }

#pragma unroll
    for (int ii = 0; ii < 4; ii++) {
        float2 lo = unpack2(acc[ii][0]);
        float2 hi = unpack2(acc[ii][1]);
        float4 v  = make_float4(lo.x * alpha, lo.y * alpha, hi.x * alpha, hi.y * alpha);
        *(float4*)&C[(size_t)(m0 + ty * 4 + ii) * ldc + n0 + tx * 4] = v;
    }
}

// ---------------- stage kernels ----------------

// Q = x @ Wq^T   [2048,1024]
__global__ void __launch_bounds__(256) k_gemm_q(const float* __restrict__ x,
                                                const float* __restrict__ Wq) {
    gemm_tile_64x64(x, DM, Wq, DM, g_Q, DM, DM, 1.0f, 0, 0);
}

// KV = x @ Wkv^T [2048,2048].  Wkv is [2048,1024] row-major -> ldb = DM.
__global__ void __launch_bounds__(256) k_gemm_kv(const float* __restrict__ x,
                                                 const float* __restrict__ Wkv) {
    gemm_tile_64x64(x, DM, Wkv, DM, g_KV, 2 * DM, DM, 1.0f, 0, 0);
}

// g_Vt[h*64+d][G*2048+k] = KV[k][G*512 + h*128 + 64 + d]  (tiled transpose)
__global__ void k_transpose_v() {
    __shared__ float tile[32][33];
    int Gh = blockIdx.z;          // 0..15
    int G = Gh >> 2, h = Gh & 3;
    int d0 = blockIdx.x * 32;     // 0 or 32
    int k0 = blockIdx.y * 32;     // key tile
    int col0 = G * 512 + h * 128 + 64 + d0;
#pragma unroll
    for (int r = threadIdx.y; r < 32; r += 8)
        tile[r][threadIdx.x] = g_KV[(size_t)(k0 + r) * 2048 + col0 + threadIdx.x];
    __syncthreads();
#pragma unroll
    for (int r = threadIdx.y; r < 32; r += 8)
        g_Vt[(size_t)(h * 64 + d0 + r) * (NG * LQ) + G * LQ + k0 + threadIdx.x] =
            tile[threadIdx.x][r];
}

// S[g][m][G][k] = SCALE * Qg[m,:] . K_G[k,:]   (z = g*4+G)
// K operand read straight from g_KV via the interleave remap (split fused).
__global__ void __launch_bounds__(256) k_gemm_s() {
    int g = blockIdx.z >> 2;
    int G = blockIdx.z & 3;
    const float* A = g_Q + g * GC;                        // lda = 1024
    float* C = g_S + (size_t)g * LQ * (NG * LQ) + G * LQ; // ldc = 8192
    gemm_tile_64x64(A, DM, g_KV, 2 * DM, C, NG * LQ, GC, SCALE, 1, G * 512);
}

// row softmax over each (g,m,G) segment of length 2048
__global__ void k_softmax() {
    __shared__ float smx[8], ssm[8];
    const int t = threadIdx.x;
    float* p = g_S + (size_t)blockIdx.x * LQ;

    float v[8];
    float mx = -INFINITY;
#pragma unroll
    for (int j = 0; j < 8; j++) {
        v[j] = p[t + 256 * j];
        mx = fmaxf(mx, v[j]);
    }
#pragma unroll
    for (int o = 16; o; o >>= 1) mx = fmaxf(mx, __shfl_xor_sync(~0u, mx, o));
    if ((t & 31) == 0) smx[t >> 5] = mx;
    __syncthreads();
    float bmax = smx[0];
#pragma unroll
    for (int i = 1; i < 8; i++) bmax = fmaxf(bmax, smx[i]);

    float s = 0.f;
#pragma unroll
    for (int j = 0; j < 8; j++) {
        v[j] = __expf(v[j] - bmax);
        s += v[j];
    }
#pragma unroll
    for (int o = 16; o; o >>= 1) s += __shfl_xor_sync(~0u, s, o);
    if ((t & 31) == 0) ssm[t >> 5] = s;
    __syncthreads();
    float tot = 0.f;
#pragma unroll
    for (int i = 0; i < 8; i++) tot += ssm[i];
    float inv = 1.0f / tot;
#pragma unroll
    for (int j = 0; j < 8; j++) p[t + 256 * j] = v[j] * inv;
}

// O[:, g*256 : g*256+256] = A_g(2048 x 8192) @ Vcat(8192 x 256)   (z = g)
__global__ void __launch_bounds__(256) k_gemm_av() {
    int g = blockIdx.z;
    const float* A = g_S + (size_t)g * LQ * (NG * LQ);   // lda = 8192
    float* C = g_O + g * GC;                             // ldc = 1024
    gemm_tile_64x64(A, NG * LQ, g_Vt, NG * LQ, C, DM, NG * LQ, 1.0f, 0, 0);
}

// P = O @ Wo^T
__global__ void __launch_bounds__(256) k_gemm_o(const float* __restrict__ Wo) {
    gemm_tile_64x64(g_O, DM, Wo, DM, g_P, DM, DM, 1.0f, 0, 0);
}

// out = LayerNorm(x + P) * gamma + beta   (biased variance)
__global__ void k_ln(const float* __restrict__ x,
                     const float* __restrict__ gamma,
                     const float* __restrict__ beta,
                     float* __restrict__ out) {
    __shared__ float s1[8], s2[8];
    const int t = threadIdx.x;
    const int m = blockIdx.x;
    const size_t base = (size_t)m * DM;

    float v[4];
    float s = 0.f, ss = 0.f;
#pragma unroll
    for (int j = 0; j < 4; j++) {
        int c = t + 256 * j;
        float y = x[base + c] + g_P[base + c];
        v[j] = y;
        s += y;
        ss += y * y;
    }
#pragma unroll
    for (int o = 16; o; o >>= 1) {
        s  += __shfl_xor_sync(~0u, s, o);
        ss += __shfl_xor_sync(~0u, ss, o);
    }
    if ((t & 31) == 0) { s1[t >> 5] = s; s2[t >> 5] = ss; }
    __syncthreads();
    float ts = 0.f, tss = 0.f;
#pragma unroll
    for (int i = 0; i < 8; i++) { ts += s1[i]; tss += s2[i]; }
    float mu = ts * (1.0f / DM);
    float var = tss * (1.0f / DM) - mu * mu;
    float inv = rsqrtf(var + LN_EPS);
#pragma unroll
    for (int j = 0; j < 4; j++) {
        int c = t + 256 * j;
        out[base + c] = gamma[c] * (v[j] - mu) * inv + beta[c];
    }
}

// ---------------- launch ----------------
extern "C" void kernel_launch(void* const* d_in, const int* in_sizes, int n_in,
                              void* d_out, int out_size) {
    const float* x     = (const float*)d_in[0];
    const float* Wq    = (const float*)d_in[1];
    const float* Wkv   = (const float*)d_in[2];
    const float* Wo    = (const float*)d_in[3];
    const float* gamma = (const float*)d_in[4];
    const float* beta  = (const float*)d_in[5];
    float* out = (float*)d_out;

    dim3 blk(256);
    k_gemm_q   <<<dim3(DM / 64, LQ / 64),          blk>>>(x, Wq);
    k_gemm_kv  <<<dim3(2 * DM / 64, LQ / 64),      blk>>>(x, Wkv);
    k_transpose_v<<<dim3(2, LQ / 32, 16), dim3(32, 8)>>>();
    k_gemm_s   <<<dim3(LQ / 64, LQ / 64, NG * NG), blk>>>();
    k_softmax  <<<NG * LQ * NG, 256>>>();
    k_gemm_av  <<<dim3(GC / 64, LQ / 64, NG),      blk>>>();
    k_gemm_o   <<<dim3(DM / 64, LQ / 64),          blk>>>(Wo);
    k_ln       <<<LQ, 256>>>(x, gamma, beta, out);
}

// round 6
// speedup vs baseline: 2.1039x; 2.1039x over previous
#include <cuda_runtime.h>
#include <cuda_bf16.h>
#include <math.h>
#include <stdint.h>

// Problem constants
#define LQ 2048
#define DM 1024
#define NG 4
#define NH 4
#define HD 64
#define GC 256            // per-group channels
#define SCALE 0.125f
#define LN_EPS 1e-5f

#define K3_PROJ (3 * DM)        // 3072
#define K3_S    (3 * GC)        // 768
#define K3_AV   (3 * NG * LQ)   // 24576
#define PAD 40                  // smem row stride (bf16) — conflict-free ldmatrix

// ---------------- scratch ----------------
__device__ __nv_bfloat16 g_x3 [LQ * K3_PROJ];
__device__ __nv_bfloat16 g_Wq3[DM * K3_PROJ];
__device__ __nv_bfloat16 g_Wkv3[2 * DM * K3_PROJ];
__device__ __nv_bfloat16 g_Wo3[DM * K3_PROJ];
__device__ float g_Q [LQ * DM];
__device__ float g_KV[LQ * 2 * DM];
__device__ __nv_bfloat16 g_Q3 [NG * LQ * K3_S];
__device__ __nv_bfloat16 g_K3 [NG * LQ * K3_S];
__device__ __nv_bfloat16 g_Vt3[GC * K3_AV];
__device__ float g_S[(size_t)NG * LQ * NG * LQ];          // 256 MB
__device__ __nv_bfloat16 g_S3[(size_t)NG * LQ * K3_AV];   // 403 MB
__device__ float g_O[LQ * DM];
__device__ __nv_bfloat16 g_O3[LQ * K3_PROJ];
__device__ float g_P[LQ * DM];

// ---------------- helpers ----------------
__device__ __forceinline__ void split_bf16(float v, __nv_bfloat16& hi, __nv_bfloat16& lo) {
    hi = __float2bfloat16(v);
    lo = __float2bfloat16(v - __bfloat162float(hi));
}
__device__ __forceinline__ unsigned smem_u32(const void* p) {
    return (unsigned)__cvta_generic_to_shared(p);
}
#define CP_ASYNC16(dst, src) \
    asm volatile("cp.async.cg.shared.global [%0], [%1], 16;" :: "r"(dst), "l"(src))
#define CP_COMMIT() asm volatile("cp.async.commit_group;")
#define CP_WAIT(n)  asm volatile("cp.async.wait_group %0;" :: "n"(n))

__device__ __forceinline__ void ldmx4(uint32_t* r, unsigned addr) {
    asm volatile("ldmatrix.sync.aligned.m8n8.x4.shared.b16 {%0,%1,%2,%3}, [%4];"
                 : "=r"(r[0]), "=r"(r[1]), "=r"(r[2]), "=r"(r[3]) : "r"(addr));
}
__device__ __forceinline__ void mma16816(float* c, const uint32_t* a, const uint32_t* b) {
    asm volatile("mma.sync.aligned.m16n8k16.row.col.f32.bf16.bf16.f32 "
                 "{%0,%1,%2,%3}, {%4,%5,%6,%7}, {%8,%9}, {%0,%1,%2,%3};"
                 : "+f"(c[0]), "+f"(c[1]), "+f"(c[2]), "+f"(c[3])
                 : "r"(a[0]), "r"(a[1]), "r"(a[2]), "r"(a[3]), "r"(b[0]), "r"(b[1]));
}

// ---------------- bf16 MMA GEMM: C(fp32, MxN tile 128x128) = alpha * A3 @ B3^T ----------------
// A3 [M][K3], B3 [N][K3] bf16 row-major; 256 threads; double-buffered cp.async.
__device__ __forceinline__ void mma_gemm_128x128(
    const __nv_bfloat16* __restrict__ A, int lda,
    const __nv_bfloat16* __restrict__ B, int ldb,
    float* __restrict__ C, int ldc, int K3, float alpha)
{
    __shared__ __align__(16) __nv_bfloat16 As[2][128 * PAD];
    __shared__ __align__(16) __nv_bfloat16 Bs[2][128 * PAD];

    const int t = threadIdx.x;
    const int lane = t & 31, w = t >> 5;
    const int wm = w & 3, wn = w >> 2;          // 4 warps along M, 2 along N
    const int m0 = blockIdx.y * 128, n0 = blockIdx.x * 128;

    const unsigned asb = smem_u32(As), bsb = smem_u32(Bs);

    float acc[2][8][4];
#pragma unroll
    for (int i = 0; i < 2; i++)
#pragma unroll
        for (int j = 0; j < 8; j++)
#pragma unroll
            for (int q = 0; q < 4; q++) acc[i][j][q] = 0.f;

    auto load_chunk = [&](int k0, int buf) {
#pragma unroll
        for (int h = 0; h < 2; h++) {
            int s = t + h * 256;                // 512 16B segments per tile
            int row = s >> 2, seg = s & 3;
            unsigned da = asb + (unsigned)(buf * 128 * PAD + row * PAD + seg * 8) * 2;
            CP_ASYNC16(da, A + (size_t)(m0 + row) * lda + k0 + seg * 8);
            unsigned db = bsb + (unsigned)(buf * 128 * PAD + row * PAD + seg * 8) * 2;
            CP_ASYNC16(db, B + (size_t)(n0 + row) * ldb + k0 + seg * 8);
        }
    };

    const int nch = K3 >> 5;                    // BK = 32
    load_chunk(0, 0);
    CP_COMMIT();

    for (int ch = 0; ch < nch; ch++) {
        int buf = ch & 1;
        if (ch + 1 < nch) {
            load_chunk((ch + 1) << 5, buf ^ 1);
            CP_COMMIT();
            CP_WAIT(1);
        } else {
            CP_WAIT(0);
        }
        __syncthreads();

#pragma unroll
        for (int kk = 0; kk < 32; kk += 16) {
            uint32_t af[2][4];
#pragma unroll
            for (int i = 0; i < 2; i++) {
                unsigned ad = asb + (unsigned)(buf * 128 * PAD +
                              (wm * 32 + i * 16 + (lane & 15)) * PAD +
                              kk + (lane >> 4) * 8) * 2;
                ldmx4(af[i], ad);
            }
            uint32_t bf[8][2];
#pragma unroll
            for (int jj = 0; jj < 4; jj++) {
                uint32_t r[4];
                unsigned bd = bsb + (unsigned)(buf * 128 * PAD +
                              (wn * 64 + jj * 16 + (lane & 15)) * PAD +
                              kk + (lane >> 4) * 8) * 2;
                ldmx4(r, bd);
                bf[2 * jj][0] = r[0]; bf[2 * jj + 1][0] = r[1];
                bf[2 * jj][1] = r[2]; bf[2 * jj + 1][1] = r[3];
            }
#pragma unroll
            for (int i = 0; i < 2; i++)
#pragma unroll
                for (int j = 0; j < 8; j++)
                    mma16816(acc[i][j], af[i], bf[j]);
        }
        __syncthreads();
    }

    const int cr = lane >> 2, cc = (lane & 3) * 2;
#pragma unroll
    for (int i = 0; i < 2; i++)
#pragma unroll
        for (int j = 0; j < 8; j++) {
            int rr = m0 + wm * 32 + i * 16 + cr;
            int c  = n0 + wn * 64 + j * 8 + cc;
            float2 v0 = make_float2(alpha * acc[i][j][0], alpha * acc[i][j][1]);
            float2 v1 = make_float2(alpha * acc[i][j][2], alpha * acc[i][j][3]);
            *(float2*)&C[(size_t)rr * ldc + c] = v0;
            *(float2*)&C[(size_t)(rr + 8) * ldc + c] = v1;
        }
}

// ---------------- conversion kernels ----------------
// A-form: [hi | lo | hi];  B-form: [hi | hi | lo]
__global__ void k_conv_a3(const float* __restrict__ src, __nv_bfloat16* __restrict__ dst, int K) {
    int idx = blockIdx.x * blockDim.x + threadIdx.x;
    int n = idx / K, k = idx % K;
    __nv_bfloat16 hi, lo; split_bf16(src[idx], hi, lo);
    size_t base = (size_t)n * 3 * K;
    dst[base + k] = hi; dst[base + K + k] = lo; dst[base + 2 * K + k] = hi;
}
__global__ void k_conv_b3(const float* __restrict__ src, __nv_bfloat16* __restrict__ dst, int K) {
    int idx = blockIdx.x * blockDim.x + threadIdx.x;
    int n = idx / K, k = idx % K;
    __nv_bfloat16 hi, lo; split_bf16(src[idx], hi, lo);
    size_t base = (size_t)n * 3 * K;
    dst[base + k] = hi; dst[base + K + k] = hi; dst[base + 2 * K + k] = lo;
}
// Q3[g][l][768] (A-form) from g_Q[l][g*256+c]
__global__ void k_conv_q3() {
    int idx = blockIdx.x * blockDim.x + threadIdx.x;   // 4*2048*256
    int c = idx & 255, l = (idx >> 8) & 2047, g = idx >> 19;
    float v = g_Q[l * DM + g * GC + c];
    __nv_bfloat16 hi, lo; split_bf16(v, hi, lo);
    size_t base = ((size_t)g * LQ + l) * K3_S;
    g_Q3[base + c] = hi; g_Q3[base + GC + c] = lo; g_Q3[base + 2 * GC + c] = hi;
}
// K3[G][l][768] (B-form) from g_KV with head interleave remap
__global__ void k_conv_k3() {
    int idx = blockIdx.x * blockDim.x + threadIdx.x;
    int c = idx & 255, l = (idx >> 8) & 2047, G = idx >> 19;
    float v = g_KV[(size_t)l * 2048 + G * 512 + ((c >> 6) * 128) + (c & 63)];
    __nv_bfloat16 hi, lo; split_bf16(v, hi, lo);
    size_t base = ((size_t)G * LQ + l) * K3_S;
    g_K3[base + c] = hi; g_K3[base + GC + c] = hi; g_K3[base + 2 * GC + c] = lo;
}
// Vt3[c][24576] (B-form): transpose of V out of g_KV
__global__ void k_conv_vt3() {
    __shared__ float tile[32][33];
    int Gh = blockIdx.z;
    int G = Gh >> 2, h = Gh & 3;
    int d0 = blockIdx.x * 32;
    int k0 = blockIdx.y * 32;
    int col0 = G * 512 + h * 128 + 64 + d0;
#pragma unroll
    for (int r = threadIdx.y; r < 32; r += 8)
        tile[r][threadIdx.x] = g_KV[(size_t)(k0 + r) * 2048 + col0 + threadIdx.x];
    __syncthreads();
#pragma unroll
    for (int r = threadIdx.y; r < 32; r += 8) {
        float v = tile[threadIdx.x][r];                 // V at (d = d0+r, k = k0+tx)
        __nv_bfloat16 hi, lo; split_bf16(v, hi, lo);
        size_t row = (size_t)(h * 64 + d0 + r) * K3_AV;
        int col = G * LQ + k0 + threadIdx.x;
        g_Vt3[row + col] = hi;
        g_Vt3[row + 8192 + col] = hi;
        g_Vt3[row + 16384 + col] = lo;
    }
}

// ---------------- GEMM wrapper kernels ----------------
__global__ void __launch_bounds__(256) k_mma_q(void) {
    mma_gemm_128x128(g_x3, K3_PROJ, g_Wq3, K3_PROJ, g_Q, DM, K3_PROJ, 1.0f);
}
__global__ void __launch_bounds__(256) k_mma_kv(void) {
    mma_gemm_128x128(g_x3, K3_PROJ, g_Wkv3, K3_PROJ, g_KV, 2 * DM, K3_PROJ, 1.0f);
}
__global__ void __launch_bounds__(256) k_mma_s(void) {
    int g = blockIdx.z >> 2, G = blockIdx.z & 3;
    const __nv_bfloat16* A = g_Q3 + (size_t)g * LQ * K3_S;
    const __nv_bfloat16* B = g_K3 + (size_t)G * LQ * K3_S;
    float* C = g_S + (size_t)g * LQ * (NG * LQ) + G * LQ;
    mma_gemm_128x128(A, K3_S, B, K3_S, C, NG * LQ, K3_S, SCALE);
}
__global__ void __launch_bounds__(256) k_mma_av(void) {
    int g = blockIdx.z;
    const __nv_bfloat16* A = g_S3 + (size_t)g * LQ * K3_AV;
    float* C = g_O + g * GC;
    mma_gemm_128x128(A, K3_AV, g_Vt3, K3_AV, C, DM, K3_AV, 1.0f);
}
__global__ void __launch_bounds__(256) k_mma_o(void) {
    mma_gemm_128x128(g_O3, K3_PROJ, g_Wo3, K3_PROJ, g_P, DM, K3_PROJ, 1.0f);
}

// ---------------- softmax fused with split-conversion (writes S3, A-form) ----------------
__global__ void k_softmax3() {
    __shared__ float smx[8], ssm[8];
    const int t = threadIdx.x;
    const int bx = blockIdx.x;                 // ((g*2048)+m)*4 + G
    const int G = bx & 3, m = (bx >> 2) & 2047, g = bx >> 13;
    const float* p = g_S + (size_t)bx * LQ;

    float v[8];
    float mx = -INFINITY;
#pragma unroll
    for (int j = 0; j < 8; j++) { v[j] = p[t + 256 * j]; mx = fmaxf(mx, v[j]); }
#pragma unroll
    for (int o = 16; o; o >>= 1) mx = fmaxf(mx, __shfl_xor_sync(~0u, mx, o));
    if ((t & 31) == 0) smx[t >> 5] = mx;
    __syncthreads();
    float bmax = smx[0];
#pragma unroll
    for (int i = 1; i < 8; i++) bmax = fmaxf(bmax, smx[i]);

    float s = 0.f;
#pragma unroll
    for (int j = 0; j < 8; j++) { v[j] = __expf(v[j] - bmax); s += v[j]; }
#pragma unroll
    for (int o = 16; o; o >>= 1) s += __shfl_xor_sync(~0u, s, o);
    if ((t & 31) == 0) ssm[t >> 5] = s;
    __syncthreads();
    float tot = 0.f;
#pragma unroll
    for (int i = 0; i < 8; i++) tot += ssm[i];
    float inv = 1.0f / tot;

    __nv_bfloat16* s3 = g_S3 + ((size_t)g * LQ + m) * K3_AV + G * LQ;
#pragma unroll
    for (int j = 0; j < 8; j++) {
        int k = t + 256 * j;
        __nv_bfloat16 hi, lo; split_bf16(v[j] * inv, hi, lo);
        s3[k] = hi;
        s3[8192 + k] = lo;
        s3[16384 + k] = hi;
    }
}

// ---------------- residual + LayerNorm ----------------
__global__ void k_ln(const float* __restrict__ x,
                     const float* __restrict__ gamma,
                     const float* __restrict__ beta,
                     float* __restrict__ out) {
    __shared__ float s1[8], s2[8];
    const int t = threadIdx.x;
    const size_t base = (size_t)blockIdx.x * DM;

    float v[4];
    float s = 0.f, ss = 0.f;
#pragma unroll
    for (int j = 0; j < 4; j++) {
        int c = t + 256 * j;
        float y = x[base + c] + g_P[base + c];
        v[j] = y; s += y; ss += y * y;
    }
#pragma unroll
    for (int o = 16; o; o >>= 1) { s += __shfl_xor_sync(~0u, s, o); ss += __shfl_xor_sync(~0u, ss, o); }
    if ((t & 31) == 0) { s1[t >> 5] = s; s2[t >> 5] = ss; }
    __syncthreads();
    float ts = 0.f, tss = 0.f;
#pragma unroll
    for (int i = 0; i < 8; i++) { ts += s1[i]; tss += s2[i]; }
    float mu = ts * (1.0f / DM);
    float var = tss * (1.0f / DM) - mu * mu;
    float inv = rsqrtf(var + LN_EPS);
#pragma unroll
    for (int j = 0; j < 4; j++) {
        int c = t + 256 * j;
        out[base + c] = gamma[c] * (v[j] - mu) * inv + beta[c];
    }
}

// ---------------- launch ----------------
extern "C" void kernel_launch(void* const* d_in, const int* in_sizes, int n_in,
                              void* d_out, int out_size) {
    const float* x     = (const float*)d_in[0];
    const float* Wq    = (const float*)d_in[1];
    const float* Wkv   = (const float*)d_in[2];
    const float* Wo    = (const float*)d_in[3];
    const float* gamma = (const float*)d_in[4];
    const float* beta  = (const float*)d_in[5];
    float* out = (float*)d_out;

    __nv_bfloat16 *px3, *pwq3, *pwkv3, *pwo3, *po3;
    cudaGetSymbolAddress((void**)&px3,  g_x3);
    cudaGetSymbolAddress((void**)&pwq3, g_Wq3);
    cudaGetSymbolAddress((void**)&pwkv3,g_Wkv3);
    cudaGetSymbolAddress((void**)&pwo3, g_Wo3);
    cudaGetSymbolAddress((void**)&po3,  g_O3);
    float *pq, *po;
    cudaGetSymbolAddress((void**)&pq, g_Q);   // unused src args resolved inside kernels
    cudaGetSymbolAddress((void**)&po, g_O);

    // operand conversions
    k_conv_a3<<<(LQ * DM) / 256, 256>>>(x, px3, DM);
    k_conv_b3<<<(DM * DM) / 256, 256>>>(Wq, pwq3, DM);
    k_conv_b3<<<(2 * DM * DM) / 256, 256>>>(Wkv, pwkv3, DM);
    k_conv_b3<<<(DM * DM) / 256, 256>>>(Wo, pwo3, DM);

    // projections
    k_mma_q <<<dim3(DM / 128, LQ / 128), 256>>>();
    k_mma_kv<<<dim3(2 * DM / 128, LQ / 128), 256>>>();

    // attention operand prep
    k_conv_q3<<<(NG * LQ * GC) / 256, 256>>>();
    k_conv_k3<<<(NG * LQ * GC) / 256, 256>>>();
    k_conv_vt3<<<dim3(2, LQ / 32, 16), dim3(32, 8)>>>();

    // scores -> softmax(+split) -> AV
    k_mma_s   <<<dim3(LQ / 128, LQ / 128, NG * NG), 256>>>();
    k_softmax3<<<NG * LQ * NG, 256>>>();
    k_mma_av  <<<dim3(GC / 128, LQ / 128, NG), 256>>>();

    // output projection + LN
    k_conv_a3<<<(LQ * DM) / 256, 256>>>(po, po3, DM);
    k_mma_o<<<dim3(DM / 128, LQ / 128), 256>>>();
    k_ln<<<LQ, 256>>>(x, gamma, beta, out);
}

// round 10
// speedup vs baseline: 5.6568x; 2.6887x over previous
#include <cuda_runtime.h>
#include <cuda_bf16.h>
#include <math.h>
#include <stdint.h>

#define LQ 2048
#define DM 1024
#define NG 4
#define NH 4
#define HD 64
#define GC 256
#define SCALE 0.125f
#define LN_EPS 1e-5f

#define K_PROJ 1024
#define K_S    256
#define K_AV   8192
#define PAD 40                  // smem row stride (bf16) — conflict-free ldmatrix

// ---------------- scratch ----------------
__device__ __align__(256) __nv_bfloat16 g_xb [LQ * DM];          // x bf16
__device__ __align__(256) __nv_bfloat16 g_Wqb[DM * DM];
__device__ __align__(256) __nv_bfloat16 g_Wkvb[2 * DM * DM];
__device__ __align__(256) __nv_bfloat16 g_Wob[DM * DM];
__device__ __align__(256) float g_Q [LQ * DM];
__device__ __align__(256) float g_KV[LQ * 2 * DM];
__device__ __align__(256) __nv_bfloat16 g_Qb [NG * LQ * GC];     // [g][l][256]
__device__ __align__(256) __nv_bfloat16 g_Kb [NG * LQ * GC];     // [G][l][256]
__device__ __align__(256) __nv_bfloat16 g_Vtb[GC * NG * LQ];     // [c][G*2048+k]
__device__ __align__(256) float g_S[(size_t)NG * LQ * NG * LQ];  // 256 MB fp32 scores
__device__ __align__(256) __nv_bfloat16 g_Pb[(size_t)NG * LQ * NG * LQ]; // probs bf16
__device__ __align__(256) float g_O[LQ * DM];
__device__ __align__(256) __nv_bfloat16 g_Ob[LQ * DM];
__device__ __align__(256) float g_P[LQ * DM];

// ---------------- helpers ----------------
__device__ __forceinline__ unsigned smem_u32(const void* p) {
    return (unsigned)__cvta_generic_to_shared(p);
}
#define CP_ASYNC16(dst, src) \
    asm volatile("cp.async.cg.shared.global [%0], [%1], 16;" :: "r"(dst), "l"(src))
#define CP_COMMIT() asm volatile("cp.async.commit_group;")
#define CP_WAIT(n)  asm volatile("cp.async.wait_group %0;" :: "n"(n))

__device__ __forceinline__ void ldmx4(uint32_t* r, unsigned addr) {
    asm volatile("ldmatrix.sync.aligned.m8n8.x4.shared.b16 {%0,%1,%2,%3}, [%4];"
                 : "=r"(r[0]), "=r"(r[1]), "=r"(r[2]), "=r"(r[3]) : "r"(addr));
}
__device__ __forceinline__ void mma16816(float* c, const uint32_t* a, const uint32_t* b) {
    asm volatile("mma.sync.aligned.m16n8k16.row.col.f32.bf16.bf16.f32 "
                 "{%0,%1,%2,%3}, {%4,%5,%6,%7}, {%8,%9}, {%0,%1,%2,%3};"
                 : "+f"(c[0]), "+f"(c[1]), "+f"(c[2]), "+f"(c[3])
                 : "r"(a[0]), "r"(a[1]), "r"(a[2]), "r"(a[3]), "r"(b[0]), "r"(b[1]));
}

// ---------------- bf16 MMA GEMM: C(fp32, 128x128 tile) = alpha * A @ B^T ----------------
// A [M][K], B [N][K] bf16 row-major; 256 threads; double-buffered cp.async; BK=32.
// ATOMIC: accumulate into C with atomicAdd (split-K).
template <bool ATOMIC>
__device__ __forceinline__ void mma_gemm_128x128(
    const __nv_bfloat16* __restrict__ A, int lda,
    const __nv_bfloat16* __restrict__ B, int ldb,
    float* __restrict__ C, int ldc, int K, float alpha)
{
    __shared__ __align__(16) __nv_bfloat16 As[2][128 * PAD];
    __shared__ __align__(16) __nv_bfloat16 Bs[2][128 * PAD];

    const int t = threadIdx.x;
    const int lane = t & 31, w = t >> 5;
    const int wm = w & 3, wn = w >> 2;          // 4 warps along M, 2 along N
    const int m0 = blockIdx.y * 128, n0 = blockIdx.x * 128;

    const unsigned asb = smem_u32(As), bsb = smem_u32(Bs);

    float acc[2][8][4];
#pragma unroll
    for (int i = 0; i < 2; i++)
#pragma unroll
        for (int j = 0; j < 8; j++)
#pragma unroll
            for (int q = 0; q < 4; q++) acc[i][j][q] = 0.f;

    auto load_chunk = [&](int k0, int buf) {
#pragma unroll
        for (int h = 0; h < 2; h++) {
            int s = t + h * 256;                // 512 16B segments per tile
            int row = s >> 2, seg = s & 3;
            unsigned da = asb + (unsigned)(buf * 128 * PAD + row * PAD + seg * 8) * 2;
            CP_ASYNC16(da, A + (size_t)(m0 + row) * lda + k0 + seg * 8);
            unsigned db = bsb + (unsigned)(buf * 128 * PAD + row * PAD + seg * 8) * 2;
            CP_ASYNC16(db, B + (size_t)(n0 + row) * ldb + k0 + seg * 8);
        }
    };

    const int nch = K >> 5;                     // BK = 32
    load_chunk(0, 0);
    CP_COMMIT();

    for (int ch = 0; ch < nch; ch++) {
        int buf = ch & 1;
        if (ch + 1 < nch) {
            load_chunk((ch + 1) << 5, buf ^ 1);
            CP_COMMIT();
            CP_WAIT(1);
        } else {
            CP_WAIT(0);
        }
        __syncthreads();

#pragma unroll
        for (int kk = 0; kk < 32; kk += 16) {
            uint32_t af[2][4];
#pragma unroll
            for (int i = 0; i < 2; i++) {
                unsigned ad = asb + (unsigned)(buf * 128 * PAD +
                              (wm * 32 + i * 16 + (lane & 15)) * PAD +
                              kk + (lane >> 4) * 8) * 2;
                ldmx4(af[i], ad);
            }
            uint32_t bf[8][2];
#pragma unroll
            for (int jj = 0; jj < 4; jj++) {
                uint32_t r[4];
                unsigned bd = bsb + (unsigned)(buf * 128 * PAD +
                              (wn * 64 + jj * 16 + (lane & 15)) * PAD +
                              kk + (lane >> 4) * 8) * 2;
                ldmx4(r, bd);
                bf[2 * jj][0] = r[0]; bf[2 * jj + 1][0] = r[1];
                bf[2 * jj][1] = r[2]; bf[2 * jj + 1][1] = r[3];
            }
#pragma unroll
            for (int i = 0; i < 2; i++)
#pragma unroll
                for (int j = 0; j < 8; j++)
                    mma16816(acc[i][j], af[i], bf[j]);
        }
        __syncthreads();
    }

    const int cr = lane >> 2, cc = (lane & 3) * 2;
#pragma unroll
    for (int i = 0; i < 2; i++)
#pragma unroll
        for (int j = 0; j < 8; j++) {
            int rr = m0 + wm * 32 + i * 16 + cr;
            int c  = n0 + wn * 64 + j * 8 + cc;
            if (ATOMIC) {
                atomicAdd(&C[(size_t)rr * ldc + c],     alpha * acc[i][j][0]);
                atomicAdd(&C[(size_t)rr * ldc + c + 1], alpha * acc[i][j][1]);
                atomicAdd(&C[(size_t)(rr + 8) * ldc + c],     alpha * acc[i][j][2]);
                atomicAdd(&C[(size_t)(rr + 8) * ldc + c + 1], alpha * acc[i][j][3]);
            } else {
                float2 v0 = make_float2(alpha * acc[i][j][0], alpha * acc[i][j][1]);
                float2 v1 = make_float2(alpha * acc[i][j][2], alpha * acc[i][j][3]);
                *(float2*)&C[(size_t)rr * ldc + c] = v0;
                *(float2*)&C[(size_t)(rr + 8) * ldc + c] = v1;
            }
        }
}

// ---------------- GEMM wrapper kernels ----------------
__global__ void __launch_bounds__(256) k_mma_q(void) {
    mma_gemm_128x128<false>(g_xb, DM, g_Wqb, DM, g_Q, DM, K_PROJ, 1.0f);
}
__global__ void __launch_bounds__(256) k_mma_kv(void) {
    mma_gemm_128x128<false>(g_xb, DM, g_Wkvb, DM, g_KV, 2 * DM, K_PROJ, 1.0f);
}
__global__ void __launch_bounds__(256) k_mma_s(void) {
    int g = blockIdx.z >> 2, G = blockIdx.z & 3;
    const __nv_bfloat16* A = g_Qb + (size_t)g * LQ * GC;
    const __nv_bfloat16* B = g_Kb + (size_t)G * LQ * GC;
    float* C = g_S + (size_t)g * LQ * (NG * LQ) + G * LQ;
    mma_gemm_128x128<false>(A, GC, B, GC, C, NG * LQ, K_S, SCALE);
}
// split-K=2: z = g*2 + ks
__global__ void __launch_bounds__(256) k_mma_av(void) {
    int g = blockIdx.z >> 1, ks = blockIdx.z & 1;
    const __nv_bfloat16* A = g_Pb + (size_t)g * LQ * (NG * LQ) + ks * (K_AV / 2);
    const __nv_bfloat16* B = g_Vtb + ks * (K_AV / 2);
    float* C = g_O + g * GC;
    mma_gemm_128x128<true>(A, NG * LQ, B, NG * LQ, C, DM, K_AV / 2, 1.0f);
}
__global__ void __launch_bounds__(256) k_mma_o(void) {
    mma_gemm_128x128<false>(g_Ob, DM, g_Wob, DM, g_P, DM, K_PROJ, 1.0f);
}

// ---------------- cast / re-layout kernels (8 elems/thread, 16B stores) ----------------
__device__ __forceinline__ uint4 cast8(const float* v) {
    __nv_bfloat16 h[8];
#pragma unroll
    for (int i = 0; i < 8; i++) h[i] = __float2bfloat16(v[i]);
    return *reinterpret_cast<uint4*>(h);
}
__global__ void k_cast_bf16(const float* __restrict__ src, __nv_bfloat16* __restrict__ dst) {
    int i8 = (blockIdx.x * blockDim.x + threadIdx.x) * 8;
    float v[8];
    *(float4*)v = *(const float4*)(src + i8);
    *(float4*)(v + 4) = *(const float4*)(src + i8 + 4);
    *(uint4*)(dst + i8) = cast8(v);
}
// Qb[g][l][256] from g_Q[l][g*256+c]
__global__ void k_conv_qb() {
    int i8 = (blockIdx.x * blockDim.x + threadIdx.x) * 8;
    int c = i8 & 255, l = (i8 >> 8) & 2047, g = i8 >> 19;
    float v[8];
    *(float4*)v = *(const float4*)(g_Q + l * DM + g * GC + c);
    *(float4*)(v + 4) = *(const float4*)(g_Q + l * DM + g * GC + c + 4);
    *(uint4*)(g_Qb + ((size_t)g * LQ + l) * GC + c) = cast8(v);
}
// Kb[G][l][256] from g_KV with head interleave remap
__global__ void k_conv_kb() {
    int i8 = (blockIdx.x * blockDim.x + threadIdx.x) * 8;
    int c = i8 & 255, l = (i8 >> 8) & 2047, G = i8 >> 19;
    const float* src = g_KV + (size_t)l * 2048 + G * 512 + ((c >> 6) * 128) + (c & 63);
    float v[8];
    *(float4*)v = *(const float4*)src;
    *(float4*)(v + 4) = *(const float4*)(src + 4);
    *(uint4*)(g_Kb + ((size_t)G * LQ + l) * GC + c) = cast8(v);
}
// Vtb[c][G*2048+k] = V(k, d) transposed out of g_KV
__global__ void k_conv_vtb() {
    __shared__ float tile[32][33];
    int Gh = blockIdx.z;
    int G = Gh >> 2, h = Gh & 3;
    int d0 = blockIdx.x * 32;
    int k0 = blockIdx.y * 32;
    int col0 = G * 512 + h * 128 + 64 + d0;
#pragma unroll
    for (int r = threadIdx.y; r < 32; r += 8)
        tile[r][threadIdx.x] = g_KV[(size_t)(k0 + r) * 2048 + col0 + threadIdx.x];
    __syncthreads();
#pragma unroll
    for (int r = threadIdx.y; r < 32; r += 8)
        g_Vtb[(size_t)(h * 64 + d0 + r) * (NG * LQ) + G * LQ + k0 + threadIdx.x] =
            __float2bfloat16(tile[threadIdx.x][r]);
}

// ---------------- softmax: fp32 scores -> bf16 probs ----------------
__global__ void k_softmax_b() {
    __shared__ float smx[8], ssm[8];
    const int t = threadIdx.x;
    const int bx = blockIdx.x;                 // ((g*2048)+m)*4 + G
    const int G = bx & 3, m = (bx >> 2) & 2047, g = bx >> 13;
    const float* p = g_S + (size_t)bx * LQ;

    float v[8];
    *(float4*)v = *(const float4*)(p + t * 8);
    *(float4*)(v + 4) = *(const float4*)(p + t * 8 + 4);
    float mx = -INFINITY;
#pragma unroll
    for (int j = 0; j < 8; j++) mx = fmaxf(mx, v[j]);
#pragma unroll
    for (int o = 16; o; o >>= 1) mx = fmaxf(mx, __shfl_xor_sync(~0u, mx, o));
    if ((t & 31) == 0) smx[t >> 5] = mx;
    __syncthreads();
    float bmax = smx[0];
#pragma unroll
    for (int i = 1; i < 8; i++) bmax = fmaxf(bmax, smx[i]);

    float s = 0.f;
#pragma unroll
    for (int j = 0; j < 8; j++) { v[j] = __expf(v[j] - bmax); s += v[j]; }
#pragma unroll
    for (int o = 16; o; o >>= 1) s += __shfl_xor_sync(~0u, s, o);
    if ((t & 31) == 0) ssm[t >> 5] = s;
    __syncthreads();
    float tot = 0.f;
#pragma unroll
    for (int i = 0; i < 8; i++) tot += ssm[i];
    float inv = 1.0f / tot;
#pragma unroll
    for (int j = 0; j < 8; j++) v[j] *= inv;

    *(uint4*)(g_Pb + ((size_t)g * LQ + m) * (NG * LQ) + G * LQ + t * 8) = cast8(v);
}

// ---------------- residual + LayerNorm ----------------
__global__ void k_ln(const float* __restrict__ x,
                     const float* __restrict__ gamma,
                     const float* __restrict__ beta,
                     float* __restrict__ out) {
    __shared__ float s1[8], s2[8];
    const int t = threadIdx.x;
    const size_t base = (size_t)blockIdx.x * DM;

    float v[4];
    float s = 0.f, ss = 0.f;
#pragma unroll
    for (int j = 0; j < 4; j++) {
        int c = t + 256 * j;
        float y = x[base + c] + g_P[base + c];
        v[j] = y; s += y; ss += y * y;
    }
#pragma unroll
    for (int o = 16; o; o >>= 1) { s += __shfl_xor_sync(~0u, s, o); ss += __shfl_xor_sync(~0u, ss, o); }
    if ((t & 31) == 0) { s1[t >> 5] = s; s2[t >> 5] = ss; }
    __syncthreads();
    float ts = 0.f, tss = 0.f;
#pragma unroll
    for (int i = 0; i < 8; i++) { ts += s1[i]; tss += s2[i]; }
    float mu = ts * (1.0f / DM);
    float var = tss * (1.0f / DM) - mu * mu;
    float inv = rsqrtf(var + LN_EPS);
#pragma unroll
    for (int j = 0; j < 4; j++) {
        int c = t + 256 * j;
        out[base + c] = gamma[c] * (v[j] - mu) * inv + beta[c];
    }
}

// ---------------- launch ----------------
extern "C" void kernel_launch(void* const* d_in, const int* in_sizes, int n_in,
                              void* d_out, int out_size) {
    const float* x     = (const float*)d_in[0];
    const float* Wq    = (const float*)d_in[1];
    const float* Wkv   = (const float*)d_in[2];
    const float* Wo    = (const float*)d_in[3];
    const float* gamma = (const float*)d_in[4];
    const float* beta  = (const float*)d_in[5];
    float* out = (float*)d_out;

    __nv_bfloat16 *pxb, *pwqb, *pwkvb, *pwob, *pob;
    cudaGetSymbolAddress((void**)&pxb,  g_xb);
    cudaGetSymbolAddress((void**)&pwqb, g_Wqb);
    cudaGetSymbolAddress((void**)&pwkvb,g_Wkvb);
    cudaGetSymbolAddress((void**)&pwob, g_Wob);
    cudaGetSymbolAddress((void**)&pob,  g_Ob);
    float *po;
    cudaGetSymbolAddress((void**)&po, g_O);

    // casts (8 elems/thread)
    k_cast_bf16<<<(LQ * DM) / 2048, 256>>>(x, pxb);
    k_cast_bf16<<<(DM * DM) / 2048, 256>>>(Wq, pwqb);
    k_cast_bf16<<<(2 * DM * DM) / 2048, 256>>>(Wkv, pwkvb);
    k_cast_bf16<<<(DM * DM) / 2048, 256>>>(Wo, pwob);

    // projections
    k_mma_q <<<dim3(DM / 128, LQ / 128), 256>>>();
    k_mma_kv<<<dim3(2 * DM / 128, LQ / 128), 256>>>();

    // attention operand prep
    k_conv_qb<<<(NG * LQ * GC) / 2048, 256>>>();
    k_conv_kb<<<(NG * LQ * GC) / 2048, 256>>>();
    k_conv_vtb<<<dim3(2, LQ / 32, 16), dim3(32, 8)>>>();

    // scores -> softmax -> AV (split-K=2 with atomic accumulate)
    k_mma_s   <<<dim3(LQ / 128, LQ / 128, NG * NG), 256>>>();
    k_softmax_b<<<NG * LQ * NG, 256>>>();
    cudaMemsetAsync(po, 0, (size_t)LQ * DM * sizeof(float));
    k_mma_av  <<<dim3(GC / 128, LQ / 128, NG * 2), 256>>>();

    // output projection + LN
    k_cast_bf16<<<(LQ * DM) / 2048, 256>>>(po, pob);
    k_mma_o<<<dim3(DM / 128, LQ / 128), 256>>>();
    k_ln<<<LQ, 256>>>(x, gamma, beta, out);
}

// round 11
// speedup vs baseline: 5.9432x; 1.0506x over previous
#include <cuda_runtime.h>
#include <cuda_bf16.h>
#include <math.h>
#include <stdint.h>

#define LQ 2048
#define DM 1024
#define NG 4
#define NH 4
#define HD 64
#define GC 256
#define SCALE 0.125f
#define LN_EPS 1e-5f

#define K_PROJ 1024
#define K_S    256
#define K_AV   8192
#define PAD 40                  // smem row stride (bf16) — conflict-free ldmatrix

// ---------------- scratch ----------------
__device__ __align__(256) __nv_bfloat16 g_xb [LQ * DM];
__device__ __align__(256) __nv_bfloat16 g_Wqb[DM * DM];
__device__ __align__(256) __nv_bfloat16 g_Wkvb[2 * DM * DM];
__device__ __align__(256) __nv_bfloat16 g_Wob[DM * DM];
__device__ __align__(256) __nv_bfloat16 g_Qb [NG * LQ * GC];     // [g][l][256]
__device__ __align__(256) __nv_bfloat16 g_Kb [NG * LQ * GC];     // [G][l][256]
__device__ __align__(256) __nv_bfloat16 g_Vb [NG * LQ * GC];     // [G][k][256]
__device__ __align__(256) __nv_bfloat16 g_Vtb[GC * NG * LQ];     // [c][G*2048+k]
__device__ __align__(256) __nv_bfloat16 g_Sb[(size_t)NG * LQ * NG * LQ]; // bf16 scores
__device__ __align__(256) __nv_bfloat16 g_Pb[(size_t)NG * LQ * NG * LQ]; // bf16 probs
__device__ __align__(256) float g_O[LQ * DM];
__device__ __align__(256) __nv_bfloat16 g_Ob[LQ * DM];
__device__ __align__(256) float g_P[LQ * DM];

// ---------------- helpers ----------------
__device__ __forceinline__ unsigned smem_u32(const void* p) {
    return (unsigned)__cvta_generic_to_shared(p);
}
__device__ __forceinline__ uint32_t pack_bf162(float a, float b) {
    __nv_bfloat162 h = __floats2bfloat162_rn(a, b);   // .x = a (low), .y = b (high)
    return *reinterpret_cast<uint32_t*>(&h);
}
#define CP_ASYNC16(dst, src) \
    asm volatile("cp.async.cg.shared.global [%0], [%1], 16;" :: "r"(dst), "l"(src))
#define CP_COMMIT() asm volatile("cp.async.commit_group;")
#define CP_WAIT(n)  asm volatile("cp.async.wait_group %0;" :: "n"(n))

__device__ __forceinline__ void ldmx4(uint32_t* r, unsigned addr) {
    asm volatile("ldmatrix.sync.aligned.m8n8.x4.shared.b16 {%0,%1,%2,%3}, [%4];"
                 : "=r"(r[0]), "=r"(r[1]), "=r"(r[2]), "=r"(r[3]) : "r"(addr));
}
__device__ __forceinline__ void mma16816(float* c, const uint32_t* a, const uint32_t* b) {
    asm volatile("mma.sync.aligned.m16n8k16.row.col.f32.bf16.bf16.f32 "
                 "{%0,%1,%2,%3}, {%4,%5,%6,%7}, {%8,%9}, {%0,%1,%2,%3};"
                 : "+f"(c[0]), "+f"(c[1]), "+f"(c[2]), "+f"(c[3])
                 : "r"(a[0]), "r"(a[1]), "r"(a[2]), "r"(a[3]), "r"(b[0]), "r"(b[1]));
}

// ---------------- bf16 MMA GEMM core: 128x128 tile of alpha * A @ B^T ----------------
// A [M][K], B [N][K] bf16 row-major; 256 threads; double-buffered cp.async; BK=32.
// Epilogue functor: epi(m, c, v0, v1) stores the pair (m,c),(m,c+1).
template <typename Epi>
__device__ __forceinline__ void mma_gemm_core(
    const __nv_bfloat16* __restrict__ A, int lda,
    const __nv_bfloat16* __restrict__ B, int ldb,
    int K, float alpha, Epi epi)
{
    __shared__ __align__(16) __nv_bfloat16 As[2][128 * PAD];
    __shared__ __align__(16) __nv_bfloat16 Bs[2][128 * PAD];

    const int t = threadIdx.x;
    const int lane = t & 31, w = t >> 5;
    const int wm = w & 3, wn = w >> 2;          // 4 warps along M, 2 along N
    const int m0 = blockIdx.y * 128, n0 = blockIdx.x * 128;

    const unsigned asb = smem_u32(As), bsb = smem_u32(Bs);

    float acc[2][8][4];
#pragma unroll
    for (int i = 0; i < 2; i++)
#pragma unroll
        for (int j = 0; j < 8; j++)
#pragma unroll
            for (int q = 0; q < 4; q++) acc[i][j][q] = 0.f;

    auto load_chunk = [&](int k0, int buf) {
#pragma unroll
        for (int h = 0; h < 2; h++) {
            int s = t + h * 256;                // 512 16B segments per tile
            int row = s >> 2, seg = s & 3;
            unsigned da = asb + (unsigned)(buf * 128 * PAD + row * PAD + seg * 8) * 2;
            CP_ASYNC16(da, A + (size_t)(m0 + row) * lda + k0 + seg * 8);
            unsigned db = bsb + (unsigned)(buf * 128 * PAD + row * PAD + seg * 8) * 2;
            CP_ASYNC16(db, B + (size_t)(n0 + row) * ldb + k0 + seg * 8);
        }
    };

    const int nch = K >> 5;                     // BK = 32
    load_chunk(0, 0);
    CP_COMMIT();

    for (int ch = 0; ch < nch; ch++) {
        int buf = ch & 1;
        if (ch + 1 < nch) {
            load_chunk((ch + 1) << 5, buf ^ 1);
            CP_COMMIT();
            CP_WAIT(1);
        } else {
            CP_WAIT(0);
        }
        __syncthreads();

#pragma unroll
        for (int kk = 0; kk < 32; kk += 16) {
            uint32_t af[2][4];
#pragma unroll
            for (int i = 0; i < 2; i++) {
                unsigned ad = asb + (unsigned)(buf * 128 * PAD +
                              (wm * 32 + i * 16 + (lane & 15)) * PAD +
                              kk + (lane >> 4) * 8) * 2;
                ldmx4(af[i], ad);
            }
            uint32_t bfr[8][2];
#pragma unroll
            for (int jj = 0; jj < 4; jj++) {
                uint32_t r[4];
                unsigned bd = bsb + (unsigned)(buf * 128 * PAD +
                              (wn * 64 + jj * 16 + (lane & 15)) * PAD +
                              kk + (lane >> 4) * 8) * 2;
                ldmx4(r, bd);
                bfr[2 * jj][0] = r[0]; bfr[2 * jj + 1][0] = r[1];
                bfr[2 * jj][1] = r[2]; bfr[2 * jj + 1][1] = r[3];
            }
#pragma unroll
            for (int i = 0; i < 2; i++)
#pragma unroll
                for (int j = 0; j < 8; j++)
                    mma16816(acc[i][j], af[i], bfr[j]);
        }
        __syncthreads();
    }

    const int cr = lane >> 2, cc = (lane & 3) * 2;
#pragma unroll
    for (int i = 0; i < 2; i++)
#pragma unroll
        for (int j = 0; j < 8; j++) {
            int rr = m0 + wm * 32 + i * 16 + cr;
            int c  = n0 + wn * 64 + j * 8 + cc;
            epi(rr, c, alpha * acc[i][j][0], alpha * acc[i][j][1]);
            epi(rr + 8, c, alpha * acc[i][j][2], alpha * acc[i][j][3]);
        }
}

// ---------------- GEMM wrapper kernels ----------------
// Q projection: epilogue writes Qb[g][l][c] bf16 directly (col n = g*256 + c)
__global__ void __launch_bounds__(256) k_mma_q(void) {
    auto epi = [](int m, int c, float a, float b) {
        int g = c >> 8, cc = c & 255;
        *(uint32_t*)&g_Qb[((size_t)g * LQ + m) * GC + cc] = pack_bf162(a, b);
    };
    mma_gemm_core(g_xb, DM, g_Wqb, DM, K_PROJ, 1.0f, epi);
}
// KV projection: col n = Gh*128 + cc; Gh = G*4+h; cc<64 -> K d=cc, cc>=64 -> V d=cc-64
__global__ void __launch_bounds__(256) k_mma_kv(void) {
    auto epi = [](int m, int c, float a, float b) {
        int Gh = c >> 7, G = Gh >> 2, h = Gh & 3, cc = c & 127;
        __nv_bfloat16* dst = (cc < 64) ? g_Kb : g_Vb;
        *(uint32_t*)&dst[((size_t)G * LQ + m) * GC + h * 64 + (cc & 63)] = pack_bf162(a, b);
    };
    mma_gemm_core(g_xb, DM, g_Wkvb, DM, K_PROJ, 1.0f, epi);
}
// Scores: bf16 output with SCALE
__global__ void __launch_bounds__(256) k_mma_s(void) {
    int g = blockIdx.z >> 2, G = blockIdx.z & 3;
    const __nv_bfloat16* A = g_Qb + (size_t)g * LQ * GC;
    const __nv_bfloat16* B = g_Kb + (size_t)G * LQ * GC;
    __nv_bfloat16* Cb = g_Sb + (size_t)g * LQ * (NG * LQ) + G * LQ;
    auto epi = [Cb](int m, int c, float a, float b) {
        *(uint32_t*)&Cb[(size_t)m * (NG * LQ) + c] = pack_bf162(a, b);
    };
    mma_gemm_core(A, GC, B, GC, K_S, SCALE, epi);
}
// AV: split-K=2, fp32 atomic accumulate into g_O
__global__ void __launch_bounds__(256) k_mma_av(void) {
    int g = blockIdx.z >> 1, ks = blockIdx.z & 1;
    const __nv_bfloat16* A = g_Pb + (size_t)g * LQ * (NG * LQ) + ks * (K_AV / 2);
    const __nv_bfloat16* B = g_Vtb + ks * (K_AV / 2);
    float* C = g_O + g * GC;
    auto epi = [C](int m, int c, float a, float b) {
        atomicAdd(&C[(size_t)m * DM + c], a);
        atomicAdd(&C[(size_t)m * DM + c + 1], b);
    };
    mma_gemm_core(A, NG * LQ, B, NG * LQ, K_AV / 2, 1.0f, epi);
}
// Output projection: fp32 store into g_P
__global__ void __launch_bounds__(256) k_mma_o(void) {
    auto epi = [](int m, int c, float a, float b) {
        *(float2*)&g_P[(size_t)m * DM + c] = make_float2(a, b);
    };
    mma_gemm_core(g_Ob, DM, g_Wob, DM, K_PROJ, 1.0f, epi);
}

// ---------------- fused cast kernel: x, Wq, Wkv, Wo -> bf16 (8 elems/thread) ----------------
__device__ __forceinline__ uint4 cast8(const float* v) {
    __nv_bfloat16 h[8];
#pragma unroll
    for (int i = 0; i < 8; i++) h[i] = __float2bfloat16(v[i]);
    return *reinterpret_cast<uint4*>(h);
}
__device__ __forceinline__ void cast_range(const float* src, __nv_bfloat16* dst, int i8) {
    float v[8];
    *(float4*)v = *(const float4*)(src + i8);
    *(float4*)(v + 4) = *(const float4*)(src + i8 + 4);
    *(uint4*)(dst + i8) = cast8(v);
}
// segments (in 8-elem units): x 256K | Wq 128K | Wkv 256K | Wo 128K  = 768K threads
__global__ void k_cast_all(const float* __restrict__ x, const float* __restrict__ Wq,
                           const float* __restrict__ Wkv, const float* __restrict__ Wo) {
    int u = blockIdx.x * blockDim.x + threadIdx.x;     // 0 .. 768K-1
    if (u < 262144)           cast_range(x,   g_xb,   u * 8);
    else if (u < 393216)      cast_range(Wq,  g_Wqb,  (u - 262144) * 8);
    else if (u < 655360)      cast_range(Wkv, g_Wkvb, (u - 393216) * 8);
    else                      cast_range(Wo,  g_Wob,  (u - 655360) * 8);
}
__global__ void k_cast_o() {
    int i8 = (blockIdx.x * blockDim.x + threadIdx.x) * 8;
    cast_range(g_O, g_Ob, i8);
}

// ---------------- V transpose (bf16 -> bf16): Vb[G][k][c] -> Vtb[c][G*2048+k] ----------------
__global__ void k_transpose_v() {
    __shared__ __nv_bfloat16 tile[32][33];
    int G = blockIdx.z;
    int c0 = blockIdx.x * 32;
    int k0 = blockIdx.y * 32;
#pragma unroll
    for (int r = threadIdx.y; r < 32; r += 8)
        tile[r][threadIdx.x] = g_Vb[((size_t)G * LQ + k0 + r) * GC + c0 + threadIdx.x];
    __syncthreads();
#pragma unroll
    for (int r = threadIdx.y; r < 32; r += 8)
        g_Vtb[(size_t)(c0 + r) * (NG * LQ) + G * LQ + k0 + threadIdx.x] =
            tile[threadIdx.x][r];
}

// ---------------- softmax: bf16 scores -> bf16 probs ----------------
__global__ void k_softmax_b() {
    __shared__ float smx[8], ssm[8];
    const int t = threadIdx.x;
    const int bx = blockIdx.x;                 // ((g*2048)+m)*4 + G
    const int G = bx & 3, m = (bx >> 2) & 2047, g = bx >> 13;
    const __nv_bfloat16* p = g_Sb + (size_t)bx * LQ;

    __nv_bfloat16 hv[8];
    *(uint4*)hv = *(const uint4*)(p + t * 8);
    float v[8];
#pragma unroll
    for (int j = 0; j < 8; j++) v[j] = __bfloat162float(hv[j]);

    float mx = -INFINITY;
#pragma unroll
    for (int j = 0; j < 8; j++) mx = fmaxf(mx, v[j]);
#pragma unroll
    for (int o = 16; o; o >>= 1) mx = fmaxf(mx, __shfl_xor_sync(~0u, mx, o));
    if ((t & 31) == 0) smx[t >> 5] = mx;
    __syncthreads();
    float bmax = smx[0];
#pragma unroll
    for (int i = 1; i < 8; i++) bmax = fmaxf(bmax, smx[i]);

    float s = 0.f;
#pragma unroll
    for (int j = 0; j < 8; j++) { v[j] = __expf(v[j] - bmax); s += v[j]; }
#pragma unroll
    for (int o = 16; o; o >>= 1) s += __shfl_xor_sync(~0u, s, o);
    if ((t & 31) == 0) ssm[t >> 5] = s;
    __syncthreads();
    float tot = 0.f;
#pragma unroll
    for (int i = 0; i < 8; i++) tot += ssm[i];
    float inv = 1.0f / tot;
#pragma unroll
    for (int j = 0; j < 8; j++) v[j] *= inv;

    *(uint4*)(g_Pb + ((size_t)g * LQ + m) * (NG * LQ) + G * LQ + t * 8) = cast8(v);
}

// ---------------- residual + LayerNorm ----------------
__global__ void k_ln(const float* __restrict__ x,
                     const float* __restrict__ gamma,
                     const float* __restrict__ beta,
                     float* __restrict__ out) {
    __shared__ float s1[8], s2[8];
    const int t = threadIdx.x;
    const size_t base = (size_t)blockIdx.x * DM;

    float v[4];
    float s = 0.f, ss = 0.f;
#pragma unroll
    for (int j = 0; j < 4; j++) {
        int c = t + 256 * j;
        float y = x[base + c] + g_P[base + c];
        v[j] = y; s += y; ss += y * y;
    }
#pragma unroll
    for (int o = 16; o; o >>= 1) { s += __shfl_xor_sync(~0u, s, o); ss += __shfl_xor_sync(~0u, ss, o); }
    if ((t & 31) == 0) { s1[t >> 5] = s; s2[t >> 5] = ss; }
    __syncthreads();
    float ts = 0.f, tss = 0.f;
#pragma unroll
    for (int i = 0; i < 8; i++) { ts += s1[i]; tss += s2[i]; }
    float mu = ts * (1.0f / DM);
    float var = tss * (1.0f / DM) - mu * mu;
    float inv = rsqrtf(var + LN_EPS);
#pragma unroll
    for (int j = 0; j < 4; j++) {
        int c = t + 256 * j;
        out[base + c] = gamma[c] * (v[j] - mu) * inv + beta[c];
    }
}

// ---------------- launch ----------------
extern "C" void kernel_launch(void* const* d_in, const int* in_sizes, int n_in,
                              void* d_out, int out_size) {
    const float* x     = (const float*)d_in[0];
    const float* Wq    = (const float*)d_in[1];
    const float* Wkv   = (const float*)d_in[2];
    const float* Wo    = (const float*)d_in[3];
    const float* gamma = (const float*)d_in[4];
    const float* beta  = (const float*)d_in[5];
    float* out = (float*)d_out;

    float* po;
    cudaGetSymbolAddress((void**)&po, g_O);

    // fused casts: 768K threads
    k_cast_all<<<3072, 256>>>(x, Wq, Wkv, Wo);

    // projections (epilogue-fused operand layouts)
    k_mma_q <<<dim3(DM / 128, LQ / 128), 256>>>();
    k_mma_kv<<<dim3(2 * DM / 128, LQ / 128), 256>>>();
    k_transpose_v<<<dim3(GC / 32, LQ / 32, NG), dim3(32, 8)>>>();

    // scores (bf16) -> softmax -> AV (split-K=2, atomic)
    k_mma_s   <<<dim3(LQ / 128, LQ / 128, NG * NG), 256>>>();
    k_softmax_b<<<NG * LQ * NG, 256>>>();
    cudaMemsetAsync(po, 0, (size_t)LQ * DM * sizeof(float));
    k_mma_av  <<<dim3(GC / 128, LQ / 128, NG * 2), 256>>>();

    // output projection + LN
    k_cast_o<<<(LQ * DM) / 2048, 256>>>();
    k_mma_o<<<dim3(DM / 128, LQ / 128), 256>>>();
    k_ln<<<LQ, 256>>>(x, gamma, beta, out);
}